// round 4
// baseline (speedup 1.0000x reference)
#include <cuda_runtime.h>
#include <math.h>

#define MBOX 512
#define CCH 512
#define POOLSZ 14
#define PP 196
#define HID 1024
#define NCLS 81
#define CONVO 256
#define KFC (CCH*PP)   /* 100352 */

#define BM 128
#define BN 128
#define BK 32
#define SPLITK 8
#define KPS (KFC/SPLITK)   /* 12544 */
#define KITERS (KPS/BK)    /* 392 */

#define BO 128   /* conv output-channel tile */

// ---------------- scratch (static device globals; no dynamic alloc) ----------------
__device__ float g_pooled[(size_t)MBOX*CCH*PP];   // ~205 MB
__device__ float g_hpre[MBOX*HID];                // fc1 accum -> relu'd in place
__device__ float g_meanz[MBOX*CONVO];

// ---------------- helpers ----------------
__device__ __forceinline__ float tf32r(float x){
    unsigned u; asm("cvt.rna.tf32.f32 %0, %1;" : "=r"(u) : "f"(x));
    return __uint_as_float(u);
}
__device__ __forceinline__ void mma_tf32(float* c, const unsigned* a, const unsigned* b){
    asm volatile("mma.sync.aligned.m16n8k8.row.col.f32.tf32.tf32.f32 "
                 "{%0,%1,%2,%3},{%4,%5,%6,%7},{%8,%9},{%0,%1,%2,%3};\n"
                 : "+f"(c[0]), "+f"(c[1]), "+f"(c[2]), "+f"(c[3])
                 : "r"(a[0]), "r"(a[1]), "r"(a[2]), "r"(a[3]),
                   "r"(b[0]), "r"(b[1]));
}

// ---------------- 0. zero split-K accumulator ----------------
__global__ void zero_hpre_kernel(){
    int i = blockIdx.x*blockDim.x + threadIdx.x;
    if (i < MBOX*HID) g_hpre[i] = 0.f;
}

// ---------------- 1. RoIAlign ----------------
__global__ void roialign_kernel(const float* __restrict__ p2, const float* __restrict__ p3,
                                const float* __restrict__ p4, const float* __restrict__ p5,
                                const float* __restrict__ boxes, const int* __restrict__ bidx,
                                const int* __restrict__ imh, const int* __restrict__ imw)
{
    int m = blockIdx.x;
    int cbase = blockIdx.y * 32;
    __shared__ float s_lx[POOLSZ], s_ly[POOLSZ];
    __shared__ int   s_x0[POOLSZ], s_x1[POOLSZ], s_y0[POOLSZ], s_y1[POOLSZ];
    __shared__ const float* s_feat;
    __shared__ int s_H, s_W;
    int tid = threadIdx.x;

    if (tid == 0){
        float bx1 = boxes[m*4+0], by1 = boxes[m*4+1];
        float bx2 = boxes[m*4+2], by2 = boxes[m*4+3];
        int hv = imh[0], wv = imw[0];
        float alpha = 224.0f/800.0f * (float)min(hv, wv);
        float bw = fabsf(bx2-bx1), bh = fabsf(by2-by1);
        float s  = sqrtf(fmaxf(bw*bh, 1e-6f));
        float kf = floorf(4.0f + log2f(s/alpha));
        int lvl  = (int)fminf(fmaxf(kf - 2.0f, 0.0f), 3.0f);
        const float* fp; int H, W; float scale;
        if      (lvl == 0){ fp = p2; H = 200; W = 200; scale = 0.25f; }
        else if (lvl == 1){ fp = p3; H = 100; W = 100; scale = 0.125f; }
        else if (lvl == 2){ fp = p4; H = 50;  W = 50;  scale = 0.0625f; }
        else              { fp = p5; H = 25;  W = 25;  scale = 0.03125f; }
        s_feat = fp; s_H = H; s_W = W;
        float sx1 = bx1*scale, sx2 = bx2*scale, sy1 = by1*scale, sy2 = by2*scale;
        for (int i = 0; i < POOLSZ; i++){
            float g  = ((float)i + 0.5f) / (float)POOLSZ;
            float xs = sx1 + g*(sx2 - sx1);
            float x0f = floorf(xs);
            s_lx[i] = xs - x0f;
            s_x0[i] = min(max((int)x0f, 0), W-1);
            s_x1[i] = min(max((int)x0f + 1, 0), W-1);
            float ys = sy1 + g*(sy2 - sy1);
            float y0f = floorf(ys);
            s_ly[i] = ys - y0f;
            s_y0[i] = min(max((int)y0f, 0), H-1);
            s_y1[i] = min(max((int)y0f + 1, 0), H-1);
        }
    }
    __syncthreads();

    const float* f = s_feat;
    int H = s_H, W = s_W;
    int b = bidx[m];

    for (int e = tid; e < 32*PP; e += blockDim.x){
        int cl  = e / PP;
        int bin = e - cl*PP;
        int py  = bin / POOLSZ, px = bin - py*POOLSZ;
        int c   = cbase + cl;
        const float* fb = f + ((size_t)(b*CCH + c)) * H * W;
        float lx = s_lx[px], ly = s_ly[py];
        int x0 = s_x0[px], x1 = s_x1[px], y0 = s_y0[py], y1 = s_y1[py];
        float f00 = fb[y0*W + x0], f01 = fb[y0*W + x1];
        float f10 = fb[y1*W + x0], f11 = fb[y1*W + x1];
        float v = f00*(1.f-ly)*(1.f-lx) + f01*(1.f-ly)*lx
                + f10*ly*(1.f-lx)       + f11*ly*lx;
        g_pooled[((size_t)m*CCH + c)*PP + bin] = v;
    }
}

// ---------------- 2. FC1 GEMM (tf32, split-K, atomics into g_hpre) ----------------
// Grid: x = M-tiles (fast-varying -> co-resident blocks share the same B panel
// in L2), y = N-tiles, z = split-K.
__global__ __launch_bounds__(256) void fc1_kernel(const float* __restrict__ Bw)
{
    __shared__ float sA[BM][36];    // [m][k] padded
    __shared__ float sB[BK][136];   // [k][n] padded
    int tid = threadIdx.x, lane = tid & 31, warp = tid >> 5;
    int wm = warp >> 2, wn = warp & 3;        // 2x4 warp grid, warp tile 64x32
    int mbase = blockIdx.x * BM;
    int nbase = blockIdx.y * BN;
    int k0    = blockIdx.z * KPS;

    float acc[4][4][4];
    for (int i = 0; i < 4; i++)
        for (int j = 0; j < 4; j++)
            for (int q = 0; q < 4; q++) acc[i][j][q] = 0.f;

    for (int it = 0; it < KITERS; it++){
        int koff = k0 + it*BK;
        for (int j = 0; j < 4; j++){
            int fidx = tid + j*256;
            int row = fidx >> 3, col = (fidx & 7) * 4;
            float4 v = *(const float4*)&g_pooled[(size_t)(mbase+row)*KFC + koff + col];
            sA[row][col+0] = tf32r(v.x); sA[row][col+1] = tf32r(v.y);
            sA[row][col+2] = tf32r(v.z); sA[row][col+3] = tf32r(v.w);
        }
        for (int j = 0; j < 4; j++){
            int fidx = tid + j*256;
            int row = fidx >> 5, col = (fidx & 31) * 4;
            float4 v = *(const float4*)&Bw[(size_t)(koff+row)*HID + nbase + col];
            sB[row][col+0] = tf32r(v.x); sB[row][col+1] = tf32r(v.y);
            sB[row][col+2] = tf32r(v.z); sB[row][col+3] = tf32r(v.w);
        }
        __syncthreads();
        #pragma unroll
        for (int ks = 0; ks < 4; ks++){
            unsigned a[4][4], bb[4][2];
            int kc = ks*8 + (lane & 3);
            #pragma unroll
            for (int mt = 0; mt < 4; mt++){
                int r = wm*64 + mt*16 + (lane >> 2);
                a[mt][0] = __float_as_uint(sA[r  ][kc  ]);
                a[mt][1] = __float_as_uint(sA[r+8][kc  ]);
                a[mt][2] = __float_as_uint(sA[r  ][kc+4]);
                a[mt][3] = __float_as_uint(sA[r+8][kc+4]);
            }
            #pragma unroll
            for (int nt = 0; nt < 4; nt++){
                int cidx = wn*32 + nt*8 + (lane >> 2);
                bb[nt][0] = __float_as_uint(sB[kc  ][cidx]);
                bb[nt][1] = __float_as_uint(sB[kc+4][cidx]);
            }
            #pragma unroll
            for (int mt = 0; mt < 4; mt++)
                #pragma unroll
                for (int nt = 0; nt < 4; nt++)
                    mma_tf32(acc[mt][nt], a[mt], bb[nt]);
        }
        __syncthreads();
    }
    for (int mt = 0; mt < 4; mt++){
        for (int nt = 0; nt < 4; nt++){
            int r = mbase + wm*64 + mt*16 + (lane >> 2);
            int c = nbase + wn*32 + nt*8 + 2*(lane & 3);
            atomicAdd(&g_hpre[(size_t)r*HID + c    ], acc[mt][nt][0]);
            atomicAdd(&g_hpre[(size_t)r*HID + c + 1], acc[mt][nt][1]);
            atomicAdd(&g_hpre[(size_t)(r+8)*HID + c    ], acc[mt][nt][2]);
            atomicAdd(&g_hpre[(size_t)(r+8)*HID + c + 1], acc[mt][nt][3]);
        }
    }
}

// ---------------- 3. bias + ReLU (in place) ----------------
__global__ void bias_relu_kernel(const float* __restrict__ bfc){
    int i = blockIdx.x*blockDim.x + threadIdx.x;
    if (i < MBOX*HID) g_hpre[i] = fmaxf(g_hpre[i] + bfc[i & (HID-1)], 0.f);
}

// ---------------- 4. conv3x3 + ReLU + spatial mean ----------------
__global__ __launch_bounds__(512) void conv_kernel(const float* __restrict__ Wc,
                                                   const float* __restrict__ bc)
{
    int m = blockIdx.y;
    int obase = blockIdx.x * BO;
    __shared__ float sW[BO][76];    // [o][k(=8ch*9)] padded
    __shared__ float sP[8*256];     // 8 ch x 16x16 zero-padded pooled tile
    __shared__ float s_sum[BO];
    int tid = threadIdx.x, lane = tid & 31, warp = tid >> 5;
    int wO = warp >> 2, wN = warp & 3;    // 4x4 warp grid, warp tile 32(o) x 56(spatial)

    if (tid < BO) s_sum[tid] = 0.f;

    int nofs[7]; unsigned nvalid = 0;
    #pragma unroll
    for (int nt = 0; nt < 7; nt++){
        int n = wN*56 + nt*8 + (lane >> 2);
        if (n < PP){
            nvalid |= 1u << nt;
            int y = n / POOLSZ, x = n - POOLSZ*y;
            nofs[nt] = y*16 + x;
        } else nofs[nt] = 0;
    }

    float acc[2][7][4];
    for (int i = 0; i < 2; i++)
        for (int j = 0; j < 7; j++)
            for (int q = 0; q < 4; q++) acc[i][j][q] = 0.f;

    for (int cb = 0; cb < CCH; cb += 8){
        for (int j = 0; j < 18; j++){                 // 128*72 = 9216 weights
            int idx = tid + j*512;
            int row = idx / 72, col = idx - row*72;
            sW[row][col] = tf32r(Wc[(size_t)(obase+row)*4608 + cb*9 + col]);
        }
        for (int j = 0; j < 4; j++){                  // 8*256 padded tile
            int idx = tid + j*512;
            int ch = idx >> 8, p = idx & 255;
            int ty = p >> 4, tx = p & 15;
            float v = 0.f;
            if (ty >= 1 && ty <= 14 && tx >= 1 && tx <= 14)
                v = g_pooled[((size_t)m*CCH + cb + ch)*PP + (ty-1)*POOLSZ + (tx-1)];
            sP[idx] = tf32r(v);
        }
        __syncthreads();
        #pragma unroll
        for (int ks = 0; ks < 9; ks++){
            unsigned a[2][4];
            int kc = ks*8 + (lane & 3);
            #pragma unroll
            for (int mt = 0; mt < 2; mt++){
                int r = wO*32 + mt*16 + (lane >> 2);
                a[mt][0] = __float_as_uint(sW[r  ][kc  ]);
                a[mt][1] = __float_as_uint(sW[r+8][kc  ]);
                a[mt][2] = __float_as_uint(sW[r  ][kc+4]);
                a[mt][3] = __float_as_uint(sW[r+8][kc+4]);
            }
            int kk0 = kc, kk1 = kc + 4;
            int ch0 = kk0/9, q0 = kk0 - 9*ch0;
            int ch1 = kk1/9, q1 = kk1 - 9*ch1;
            int boff0 = ch0*256 + (q0/3)*16 + (q0 - 3*(q0/3));
            int boff1 = ch1*256 + (q1/3)*16 + (q1 - 3*(q1/3));
            #pragma unroll
            for (int nt = 0; nt < 7; nt++){
                unsigned bb[2] = {0u, 0u};
                if ((nvalid >> nt) & 1){
                    bb[0] = __float_as_uint(sP[boff0 + nofs[nt]]);
                    bb[1] = __float_as_uint(sP[boff1 + nofs[nt]]);
                }
                mma_tf32(acc[0][nt], a[0], bb);
                mma_tf32(acc[1][nt], a[1], bb);
            }
        }
        __syncthreads();
    }

    // epilogue: ReLU(z + bias), sum over valid spatial, reduce
    #pragma unroll
    for (int mt = 0; mt < 2; mt++){
        int rrel = wO*32 + mt*16 + (lane >> 2);
        float bv0 = bc[obase + rrel], bv1 = bc[obase + rrel + 8];
        float s0 = 0.f, s1 = 0.f;
        #pragma unroll
        for (int nt = 0; nt < 7; nt++){
            #pragma unroll
            for (int j = 0; j < 2; j++){
                int n = wN*56 + nt*8 + 2*(lane & 3) + j;
                if (n < PP){
                    s0 += fmaxf(acc[mt][nt][j]   + bv0, 0.f);
                    s1 += fmaxf(acc[mt][nt][2+j] + bv1, 0.f);
                }
            }
        }
        s0 += __shfl_xor_sync(0xffffffffu, s0, 1);
        s0 += __shfl_xor_sync(0xffffffffu, s0, 2);
        s1 += __shfl_xor_sync(0xffffffffu, s1, 1);
        s1 += __shfl_xor_sync(0xffffffffu, s1, 2);
        if ((lane & 3) == 0){
            atomicAdd(&s_sum[rrel    ], s0);
            atomicAdd(&s_sum[rrel + 8], s1);
        }
    }
    __syncthreads();
    if (tid < BO)
        g_meanz[(size_t)m*CONVO + obase + tid] = s_sum[tid] * (1.0f/196.0f);
}

// ---------------- 5. cls/box heads + softmax ----------------
__global__ void clsbox_kernel(const float* __restrict__ wc, const float* __restrict__ bcl,
                              const float* __restrict__ wb, const float* __restrict__ bb,
                              float* __restrict__ out)
{
    int m = blockIdx.x, tid = threadIdx.x;
    __shared__ float sh[HID];
    __shared__ float sl[NCLS];
    __shared__ float s_red[4];
    for (int i = tid; i < HID; i += blockDim.x) sh[i] = g_hpre[(size_t)m*HID + i];
    __syncthreads();
    if (tid < NCLS){
        float ac = 0.f, ab = 0.f;
        for (int k = 0; k < HID; k++){
            float hv = sh[k];
            ac = fmaf(wc[k*NCLS + tid], hv, ac);
            ab = fmaf(wb[k*NCLS + tid], hv, ab);
        }
        sl[tid] = ac + bcl[tid];
        out[MBOX*NCLS + m*NCLS + tid] = ab + bb[tid];
    }
    __syncthreads();
    {
        float v = (tid < NCLS) ? sl[tid] : -1e30f;
        float mx = v;
        #pragma unroll
        for (int o = 16; o > 0; o >>= 1) mx = fmaxf(mx, __shfl_xor_sync(0xffffffffu, mx, o));
        if ((tid & 31) == 0) s_red[tid >> 5] = mx;
        __syncthreads();
        float gmx = fmaxf(fmaxf(s_red[0], s_red[1]), fmaxf(s_red[2], s_red[3]));
        float e = (tid < NCLS) ? expf(v - gmx) : 0.f;
        float sm = e;
        #pragma unroll
        for (int o = 16; o > 0; o >>= 1) sm += __shfl_xor_sync(0xffffffffu, sm, o);
        __syncthreads();
        if ((tid & 31) == 0) s_red[tid >> 5] = sm;
        __syncthreads();
        float gsm = s_red[0] + s_red[1] + s_red[2] + s_red[3];
        if (tid < NCLS)
            out[m*NCLS + tid] = e / gsm;
    }
}

// ---------------- 6. mask head ----------------
__global__ void mask_kernel(const float* __restrict__ wm, const float* __restrict__ bm,
                            float* __restrict__ out)
{
    int m = blockIdx.x, tid = threadIdx.x;
    __shared__ float sz[CONVO];
    for (int i = tid; i < CONVO; i += blockDim.x) sz[i] = g_meanz[(size_t)m*CONVO + i];
    __syncthreads();
    if (tid < NCLS){
        float a = 0.f;
        for (int k = 0; k < CONVO; k++) a = fmaf(wm[k*NCLS + tid], sz[k], a);
        a += bm[tid];
        out[2*MBOX*NCLS + m*NCLS + tid] = 1.f / (1.f + expf(-a));
    }
}

// ---------------- launch ----------------
extern "C" void kernel_launch(void* const* d_in, const int* in_sizes, int n_in,
                              void* d_out, int out_size)
{
    const float* p2     = (const float*)d_in[0];
    const float* p3     = (const float*)d_in[1];
    const float* p4     = (const float*)d_in[2];
    const float* p5     = (const float*)d_in[3];
    const float* boxes  = (const float*)d_in[4];
    const int*   bidx   = (const int*)  d_in[5];
    const float* w_fc1  = (const float*)d_in[6];
    const float* b_fc1  = (const float*)d_in[7];
    const float* w_cls  = (const float*)d_in[8];
    const float* b_cls  = (const float*)d_in[9];
    const float* w_box  = (const float*)d_in[10];
    const float* b_box  = (const float*)d_in[11];
    const float* w_conv = (const float*)d_in[12];
    const float* b_conv = (const float*)d_in[13];
    const float* w_mfc  = (const float*)d_in[14];
    const float* b_mfc  = (const float*)d_in[15];
    const int*   imh    = (const int*)  d_in[16];
    const int*   imw    = (const int*)  d_in[17];
    float* out = (float*)d_out;

    zero_hpre_kernel<<<(MBOX*HID + 255)/256, 256>>>();
    roialign_kernel<<<dim3(MBOX, CCH/32), 256>>>(p2, p3, p4, p5, boxes, bidx, imh, imw);
    fc1_kernel<<<dim3(MBOX/BM, HID/BN, SPLITK), 256>>>(w_fc1);
    bias_relu_kernel<<<(MBOX*HID + 255)/256, 256>>>(b_fc1);
    conv_kernel<<<dim3(CONVO/BO, MBOX), 512>>>(w_conv, b_conv);
    clsbox_kernel<<<MBOX, 128>>>(w_cls, b_cls, w_box, b_box, out);
    mask_kernel<<<MBOX, 128>>>(w_mfc, b_mfc, out);
}